// round 13
// baseline (speedup 1.0000x reference)
#include <cuda_runtime.h>

#define NN 16384
#define E_EDGES 524288
#define KNB 16
#define NSEG 8
#define JSEG (NN/NSEG)
#define JCHUNK 128

// ---------------- scratch (static device globals; no allocations) ----------------
__device__ float g_x1[NN*64];
__device__ float g_u [NN*64];
__device__ float g_v [NN*64];
__device__ float g_sq[NN];
__device__ int   g_knn[NN*KNB];
__device__ float g_pd[NSEG*NN*KNB];
__device__ int   g_pi[NSEG*NN*KNB];
__device__ int   g_ei32;   // 1 if edge_index buffer is int32, 0 if int64

// ---------------- f32x2 helpers ----------------
static __device__ __forceinline__ unsigned long long pk2(float lo, float hi){
    unsigned long long r;
    asm("mov.b64 %0, {%1,%2};" : "=l"(r) : "f"(lo), "f"(hi));
    return r;
}
static __device__ __forceinline__ void fma2(unsigned long long& acc,
                                            unsigned long long a, unsigned long long b){
    asm("fma.rn.f32x2 %0, %1, %2, %0;" : "+l"(acc) : "l"(a), "l"(b));
}
static __device__ __forceinline__ float2 upk2(unsigned long long v){
    float lo, hi;
    asm("mov.b64 {%0,%1}, %2;" : "=f"(lo), "=f"(hi) : "l"(v));
    return make_float2(lo, hi);
}

// Insert (d,j) into register-resident top-16, evicting the lexicographic max (d,idx).
static __device__ __forceinline__ void t16_insert(float (&bd)[16], int (&bi)[16],
                                                  float d, int j, float& mx, int& mxi){
    int pos = 0; float cd = bd[0]; int ci = bi[0];
#pragma unroll
    for (int t = 1; t < 16; t++){
        bool g = (bd[t] > cd) || (bd[t] == cd && bi[t] > ci);
        cd = g ? bd[t] : cd; ci = g ? bi[t] : ci; pos = g ? t : pos;
    }
#pragma unroll
    for (int t = 0; t < 16; t++) if (t == pos){ bd[t] = d; bi[t] = j; }
    cd = bd[0]; ci = bi[0];
#pragma unroll
    for (int t = 1; t < 16; t++){
        bool g = (bd[t] > cd) || (bd[t] == cd && bi[t] > ci);
        cd = g ? bd[t] : cd; ci = g ? bi[t] : ci;
    }
    mx = cd; mxi = ci;
}

// ---------------- edge_index dtype detection ----------------
__global__ void k_detect(const int* __restrict__ ei){
    __shared__ int nz;
    if (threadIdx.x == 0) nz = 0;
    __syncthreads();
    int c = 0;
    for (int t = threadIdx.x; t < 4096; t += blockDim.x)
        if (ei[2*t + 1] != 0) c = 1;
    if (c) atomicOr(&nz, 1);
    __syncthreads();
    if (threadIdx.x == 0) g_ei32 = nz;
}

// ---------------- init: zero x1 accumulator and output ----------------
__global__ void k_init(float* __restrict__ out){
    int i = blockIdx.x*blockDim.x + threadIdx.x;
    if (i < NN*64){ g_x1[i] = 0.f; out[i] = 0.f; }
}

// ---------------- per-node affine split of layer 1 ----------------
template<int CIN, bool SQ, bool FROMX1>
__global__ void __launch_bounds__(256) k_node(const float* __restrict__ xin,
                                              const float* __restrict__ W,
                                              const float* __restrict__ bias){
    __shared__ __align__(16) float sW[2*CIN*64];
    __shared__ __align__(16) float sb[64];
    for (int t = threadIdx.x; t < 2*CIN*64; t += blockDim.x) sW[t] = W[t];
    if (threadIdx.x < 64) sb[threadIdx.x] = bias[threadIdx.x];
    __syncthreads();

    int i = blockIdx.x*blockDim.x + threadIdx.x;
    const float* xb = FROMX1 ? (const float*)g_x1 : xin;
    float xr[CIN];
#pragma unroll
    for (int k = 0; k < CIN; k++) xr[k] = xb[i*CIN + k];
    if (SQ){
        float s = 0.f;
#pragma unroll
        for (int k = 0; k < CIN; k++) s += xr[k]*xr[k];
        g_sq[i] = s;
    }
    for (int cq = 0; cq < 16; cq++){
        float4 au = make_float4(0.f,0.f,0.f,0.f);
        float4 av = make_float4(0.f,0.f,0.f,0.f);
#pragma unroll
        for (int k = 0; k < CIN; k++){
            float4 wt = *(const float4*)(sW + k*64 + cq*4);
            float4 wb = *(const float4*)(sW + (CIN+k)*64 + cq*4);
            float p = xr[k];
            au.x += p*wt.x; au.y += p*wt.y; au.z += p*wt.z; au.w += p*wt.w;
            av.x += p*wb.x; av.y += p*wb.y; av.z += p*wb.z; av.w += p*wb.w;
        }
        float4 bb = *(const float4*)(sb + cq*4);
        float4 uo;
        uo.x = bb.x + au.x - av.x; uo.y = bb.y + au.y - av.y;
        uo.z = bb.z + au.z - av.z; uo.w = bb.w + au.w - av.w;
        *(float4*)(g_u + i*64 + cq*4) = uo;
        *(float4*)(g_v + i*64 + cq*4) = av;
    }
}

// ---------------- per-edge: ReLU(u+v) -> 64x64 layer-2 -> ReLU -> atomic seg-max ----------
static __device__ __forceinline__ void edge_tail(int dst, int src,
                                                 const float* __restrict__ sWt,
                                                 const float* __restrict__ sb,
                                                 float* __restrict__ outb){
    const float4* up = (const float4*)(g_u + dst*64);
    const float4* vp = (const float4*)(g_v + src*64);
    unsigned long long h1p[32];
#pragma unroll
    for (int q = 0; q < 16; q++){
        float4 a = up[q], b = vp[q];
        h1p[2*q  ] = pk2(fmaxf(a.x+b.x,0.f), fmaxf(a.y+b.y,0.f));
        h1p[2*q+1] = pk2(fmaxf(a.z+b.z,0.f), fmaxf(a.w+b.w,0.f));
    }
    int* orow = (int*)outb + dst*64;
    for (int c = 0; c < 64; c++){
        const ulonglong2* w = (const ulonglong2*)(sWt + c*64);
        unsigned long long a0 = pk2(sb[c], 0.f), a1 = 0ull, a2 = 0ull, a3 = 0ull;
#pragma unroll
        for (int q = 0; q < 16; q += 2){
            ulonglong2 w0 = w[q], w1 = w[q+1];
            fma2(a0, h1p[2*q  ], w0.x);
            fma2(a1, h1p[2*q+1], w0.y);
            fma2(a2, h1p[2*q+2], w1.x);
            fma2(a3, h1p[2*q+3], w1.y);
        }
        float2 r0 = upk2(a0), r1 = upk2(a1), r2 = upk2(a2), r3 = upk2(a3);
        float s = ((r0.x+r0.y)+(r1.x+r1.y)) + ((r2.x+r2.y)+(r3.x+r3.y));
        if (s > 0.f) atomicMax(orow + c, __float_as_int(s));  // non-negative floats: int-max == float-max
    }
}

__global__ void __launch_bounds__(256) k_ec1(const void* __restrict__ ei,
                                             const float* __restrict__ W2,
                                             const float* __restrict__ b2){
    __shared__ __align__(16) float sWt[64*64];
    __shared__ __align__(16) float sb[64];
    for (int t = threadIdx.x; t < 4096; t += blockDim.x){
        int k = t >> 6, c = t & 63;
        sWt[c*64 + k] = W2[t];                       // transpose: contiguous over k
    }
    if (threadIdx.x < 64) sb[threadIdx.x] = b2[threadIdx.x];
    __syncthreads();
    int e = blockIdx.x*blockDim.x + threadIdx.x;
    int src, dst;
    if (g_ei32){
        const int* e32 = (const int*)ei;
        src = e32[e];                    // edge_index[0] = source j
        dst = e32[E_EDGES + e];          // edge_index[1] = target i
    } else {
        const long long* e64 = (const long long*)ei;
        src = (int)e64[e];
        dst = (int)e64[E_EDGES + e];
    }
    if ((unsigned)src < NN && (unsigned)dst < NN)
        edge_tail(dst, src, sWt, sb, g_x1);
}

__global__ void __launch_bounds__(256) k_ec2(const float* __restrict__ W4,
                                             const float* __restrict__ b4,
                                             float* __restrict__ out){
    __shared__ __align__(16) float sWt[64*64];
    __shared__ __align__(16) float sb[64];
    for (int t = threadIdx.x; t < 4096; t += blockDim.x){
        int k = t >> 6, c = t & 63;
        sWt[c*64 + k] = W4[t];
    }
    if (threadIdx.x < 64) sb[threadIdx.x] = b4[threadIdx.x];
    __syncthreads();
    int e = blockIdx.x*blockDim.x + threadIdx.x;
    int dst = e >> 4;
    int src = g_knn[e];
    edge_tail(dst, src, sWt, sb, out);
}

// ---------------- kNN: 2 rows per thread, per-row top-16 over one j-segment ----------------
// __launch_bounds__(128, 1): allow up to 255 regs (the old (128,4) capped at 128 and spilled).
__global__ void __launch_bounds__(128, 1) k_knn(){
    __shared__ __align__(16) float sxj[JCHUNK*64];
    __shared__ float ssq[JCHUNK];
    int tid  = threadIdx.x;
    int row0 = blockIdx.x*256 + tid;       // rows [b*256, b*256+128)
    int row1 = row0 + 128;                 // rows [b*256+128, b*256+256)
    int j0   = blockIdx.y*JSEG;

    unsigned long long x0[32], x1[32];
    {
        const ulonglong2* p0 = (const ulonglong2*)(g_x1 + row0*64);
        const ulonglong2* p1 = (const ulonglong2*)(g_x1 + row1*64);
#pragma unroll
        for (int q = 0; q < 16; q++){
            ulonglong2 t0 = p0[q]; x0[2*q] = t0.x; x0[2*q+1] = t0.y;
            ulonglong2 t1 = p1[q]; x1[2*q] = t1.x; x1[2*q+1] = t1.y;
        }
    }
    float sq0 = g_sq[row0];
    float sq1 = g_sq[row1];

    float bd0[16], bd1[16]; int bi0[16], bi1[16];
#pragma unroll
    for (int t = 0; t < 16; t++){
        bd0[t] = __int_as_float(0x7f800000); bi0[t] = 0x7fffffff;
        bd1[t] = __int_as_float(0x7f800000); bi1[t] = 0x7fffffff;
    }
    float mx0 = __int_as_float(0x7f800000); int mxi0 = 0x7fffffff;
    float mx1 = __int_as_float(0x7f800000); int mxi1 = 0x7fffffff;

    for (int ch = 0; ch < JSEG; ch += JCHUNK){
        __syncthreads();
        const float4* gs = (const float4*)(g_x1 + (size_t)(j0+ch)*64);
        float4* sd = (float4*)sxj;
#pragma unroll
        for (int t = 0; t < (JCHUNK*16)/128; t++) sd[tid + t*128] = gs[tid + t*128];
        if (tid < JCHUNK) ssq[tid] = g_sq[j0 + ch + tid];
        __syncthreads();

        for (int jj = 0; jj < JCHUNK; jj++){
            const ulonglong2* sp = (const ulonglong2*)(sxj + jj*64);
            unsigned long long a0=0ull,a1=0ull,a2=0ull,a3=0ull;
            unsigned long long b0=0ull,b1=0ull,b2=0ull,b3=0ull;
#pragma unroll
            for (int q = 0; q < 16; q += 2){
                ulonglong2 w0 = sp[q], w1 = sp[q+1];
                fma2(a0, x0[2*q  ], w0.x);  fma2(b0, x1[2*q  ], w0.x);
                fma2(a1, x0[2*q+1], w0.y);  fma2(b1, x1[2*q+1], w0.y);
                fma2(a2, x0[2*q+2], w1.x);  fma2(b2, x1[2*q+2], w1.x);
                fma2(a3, x0[2*q+3], w1.y);  fma2(b3, x1[2*q+3], w1.y);
            }
            float sqj = ssq[jj];
            int j = j0 + ch + jj;
            {
                float2 r0 = upk2(a0), r1 = upk2(a1), r2 = upk2(a2), r3 = upk2(a3);
                float dot = ((r0.x+r0.y)+(r1.x+r1.y)) + ((r2.x+r2.y)+(r3.x+r3.y));
                float d = sq0 + sqj - 2.f*dot;
                // ascending j + strict < reproduces lax.top_k tie order exactly
                if (d < mx0) t16_insert(bd0, bi0, d, j, mx0, mxi0);
            }
            {
                float2 r0 = upk2(b0), r1 = upk2(b1), r2 = upk2(b2), r3 = upk2(b3);
                float dot = ((r0.x+r0.y)+(r1.x+r1.y)) + ((r2.x+r2.y)+(r3.x+r3.y));
                float d = sq1 + sqj - 2.f*dot;
                if (d < mx1) t16_insert(bd1, bi1, d, j, mx1, mxi1);
            }
        }
    }
    int base0 = (blockIdx.y*NN + row0)*KNB;
    int base1 = (blockIdx.y*NN + row1)*KNB;
#pragma unroll
    for (int t = 0; t < 16; t++){
        g_pd[base0+t] = bd0[t]; g_pi[base0+t] = bi0[t];
        g_pd[base1+t] = bd1[t]; g_pi[base1+t] = bi1[t];
    }
}

// ---------------- merge per-segment top-16s into global top-16 set ----------------
__global__ void __launch_bounds__(256) k_merge(){
    int i = blockIdx.x*blockDim.x + threadIdx.x;
    float bd[16]; int bi[16];
#pragma unroll
    for (int t = 0; t < 16; t++){ bd[t] = __int_as_float(0x7f800000); bi[t] = 0x7fffffff; }
    float mx = __int_as_float(0x7f800000); int mxi = 0x7fffffff;
    for (int s = 0; s < NSEG; s++){
        int base = (s*NN + i)*KNB;
#pragma unroll
        for (int t = 0; t < 16; t++){
            float d = g_pd[base+t]; int j = g_pi[base+t];
            if (d < mx || (d == mx && j < mxi)){
                t16_insert(bd, bi, d, j, mx, mxi);
            }
        }
    }
#pragma unroll
    for (int t = 0; t < 16; t++) g_knn[i*KNB + t] = bi[t];
}

// ---------------- launch ----------------
extern "C" void kernel_launch(void* const* d_in, const int* in_sizes, int n_in,
                              void* d_out, int out_size){
    const float* x  = (const float*)d_in[0];
    const void*  ei = d_in[1];
    int off = (n_in > 2 && in_sizes[2] == 1) ? 3 : 2;
    const float* W1 = (const float*)d_in[off+0];
    const float* b1 = (const float*)d_in[off+1];
    const float* W2 = (const float*)d_in[off+2];
    const float* b2 = (const float*)d_in[off+3];
    const float* W3 = (const float*)d_in[off+4];
    const float* b3 = (const float*)d_in[off+5];
    const float* W4 = (const float*)d_in[off+6];
    const float* b4 = (const float*)d_in[off+7];
    float* out = (float*)d_out;

    k_detect<<<1, 256>>>((const int*)ei);
    k_init<<<(NN*64)/256, 256>>>(out);
    // EdgeConv1
    k_node<3, false, false><<<NN/256, 256>>>(x, W1, b1);
    k_ec1<<<E_EDGES/256, 256>>>(ei, W2, b2);
    // node-level work for EdgeConv2 layer-1 + sq-norms of x1 for kNN
    k_node<64, true, true><<<NN/256, 256>>>(nullptr, W3, b3);
    // kNN in x1 feature space (2 rows/thread)
    dim3 kg(NN/256, NSEG);
    k_knn<<<kg, 128>>>();
    k_merge<<<NN/256, 256>>>();
    // EdgeConv2
    k_ec2<<<(NN*KNB)/256, 256>>>(W4, b4, out);
    (void)in_sizes; (void)n_in; (void)out_size;
}

// round 14
// speedup vs baseline: 1.4418x; 1.4418x over previous
#include <cuda_runtime.h>

#define NN 16384
#define E_EDGES 524288
#define KNB 16
#define NSEG 2
#define JSEG (NN/NSEG)
#define JCHUNK 128

// ---------------- scratch (static device globals; no allocations) ----------------
__device__ float g_x1[NN*64];
__device__ float g_u [NN*64];
__device__ float g_v [NN*64];
__device__ float g_sq[NN];
__device__ int   g_knn[NN*KNB];
__device__ float g_pd[NSEG*NN*KNB];
__device__ int   g_pi[NSEG*NN*KNB];
__device__ int   g_ei32;   // 1 if edge_index buffer is int32, 0 if int64

// ---------------- f32x2 helpers ----------------
static __device__ __forceinline__ unsigned long long pk2(float lo, float hi){
    unsigned long long r;
    asm("mov.b64 %0, {%1,%2};" : "=l"(r) : "f"(lo), "f"(hi));
    return r;
}
static __device__ __forceinline__ void fma2(unsigned long long& acc,
                                            unsigned long long a, unsigned long long b){
    asm("fma.rn.f32x2 %0, %1, %2, %0;" : "+l"(acc) : "l"(a), "l"(b));
}
static __device__ __forceinline__ float2 upk2(unsigned long long v){
    float lo, hi;
    asm("mov.b64 {%0,%1}, %2;" : "=f"(lo), "=f"(hi) : "l"(v));
    return make_float2(lo, hi);
}

// Insert (d,j) into register-resident top-16, evicting the lexicographic max (d,idx).
static __device__ __forceinline__ void t16_insert(float (&bd)[16], int (&bi)[16],
                                                  float d, int j, float& mx, int& mxi){
    int pos = 0; float cd = bd[0]; int ci = bi[0];
#pragma unroll
    for (int t = 1; t < 16; t++){
        bool g = (bd[t] > cd) || (bd[t] == cd && bi[t] > ci);
        cd = g ? bd[t] : cd; ci = g ? bi[t] : ci; pos = g ? t : pos;
    }
#pragma unroll
    for (int t = 0; t < 16; t++) if (t == pos){ bd[t] = d; bi[t] = j; }
    cd = bd[0]; ci = bi[0];
#pragma unroll
    for (int t = 1; t < 16; t++){
        bool g = (bd[t] > cd) || (bd[t] == cd && bi[t] > ci);
        cd = g ? bd[t] : cd; ci = g ? bi[t] : ci;
    }
    mx = cd; mxi = ci;
}

// ---------------- edge_index dtype detection ----------------
__global__ void k_detect(const int* __restrict__ ei){
    __shared__ int nz;
    if (threadIdx.x == 0) nz = 0;
    __syncthreads();
    int c = 0;
    for (int t = threadIdx.x; t < 4096; t += blockDim.x)
        if (ei[2*t + 1] != 0) c = 1;
    if (c) atomicOr(&nz, 1);
    __syncthreads();
    if (threadIdx.x == 0) g_ei32 = nz;
}

// ---------------- init: zero x1 accumulator and output ----------------
__global__ void k_init(float* __restrict__ out){
    int i = blockIdx.x*blockDim.x + threadIdx.x;
    if (i < NN*64){ g_x1[i] = 0.f; out[i] = 0.f; }
}

// ---------------- per-node affine split of layer 1 ----------------
template<int CIN, bool SQ, bool FROMX1>
__global__ void __launch_bounds__(256) k_node(const float* __restrict__ xin,
                                              const float* __restrict__ W,
                                              const float* __restrict__ bias){
    __shared__ __align__(16) float sW[2*CIN*64];
    __shared__ __align__(16) float sb[64];
    for (int t = threadIdx.x; t < 2*CIN*64; t += blockDim.x) sW[t] = W[t];
    if (threadIdx.x < 64) sb[threadIdx.x] = bias[threadIdx.x];
    __syncthreads();

    int i = blockIdx.x*blockDim.x + threadIdx.x;
    const float* xb = FROMX1 ? (const float*)g_x1 : xin;
    float xr[CIN];
#pragma unroll
    for (int k = 0; k < CIN; k++) xr[k] = xb[i*CIN + k];
    if (SQ){
        float s = 0.f;
#pragma unroll
        for (int k = 0; k < CIN; k++) s += xr[k]*xr[k];
        g_sq[i] = s;
    }
    for (int cq = 0; cq < 16; cq++){
        float4 au = make_float4(0.f,0.f,0.f,0.f);
        float4 av = make_float4(0.f,0.f,0.f,0.f);
#pragma unroll
        for (int k = 0; k < CIN; k++){
            float4 wt = *(const float4*)(sW + k*64 + cq*4);
            float4 wb = *(const float4*)(sW + (CIN+k)*64 + cq*4);
            float p = xr[k];
            au.x += p*wt.x; au.y += p*wt.y; au.z += p*wt.z; au.w += p*wt.w;
            av.x += p*wb.x; av.y += p*wb.y; av.z += p*wb.z; av.w += p*wb.w;
        }
        float4 bb = *(const float4*)(sb + cq*4);
        float4 uo;
        uo.x = bb.x + au.x - av.x; uo.y = bb.y + au.y - av.y;
        uo.z = bb.z + au.z - av.z; uo.w = bb.w + au.w - av.w;
        *(float4*)(g_u + i*64 + cq*4) = uo;
        *(float4*)(g_v + i*64 + cq*4) = av;
    }
}

// ---------------- per-edge: ReLU(u+v) -> 64x64 layer-2 -> ReLU -> atomic seg-max ----------
static __device__ __forceinline__ void edge_tail(int dst, int src,
                                                 const float* __restrict__ sWt,
                                                 const float* __restrict__ sb,
                                                 float* __restrict__ outb){
    const float4* up = (const float4*)(g_u + dst*64);
    const float4* vp = (const float4*)(g_v + src*64);
    unsigned long long h1p[32];
#pragma unroll
    for (int q = 0; q < 16; q++){
        float4 a = up[q], b = vp[q];
        h1p[2*q  ] = pk2(fmaxf(a.x+b.x,0.f), fmaxf(a.y+b.y,0.f));
        h1p[2*q+1] = pk2(fmaxf(a.z+b.z,0.f), fmaxf(a.w+b.w,0.f));
    }
    int* orow = (int*)outb + dst*64;
    for (int c = 0; c < 64; c++){
        const ulonglong2* w = (const ulonglong2*)(sWt + c*64);
        unsigned long long a0 = pk2(sb[c], 0.f), a1 = 0ull, a2 = 0ull, a3 = 0ull;
#pragma unroll
        for (int q = 0; q < 16; q += 2){
            ulonglong2 w0 = w[q], w1 = w[q+1];
            fma2(a0, h1p[2*q  ], w0.x);
            fma2(a1, h1p[2*q+1], w0.y);
            fma2(a2, h1p[2*q+2], w1.x);
            fma2(a3, h1p[2*q+3], w1.y);
        }
        float2 r0 = upk2(a0), r1 = upk2(a1), r2 = upk2(a2), r3 = upk2(a3);
        float s = ((r0.x+r0.y)+(r1.x+r1.y)) + ((r2.x+r2.y)+(r3.x+r3.y));
        if (s > 0.f) atomicMax(orow + c, __float_as_int(s));  // non-negative floats: int-max == float-max
    }
}

__global__ void __launch_bounds__(256) k_ec1(const void* __restrict__ ei,
                                             const float* __restrict__ W2,
                                             const float* __restrict__ b2){
    __shared__ __align__(16) float sWt[64*64];
    __shared__ __align__(16) float sb[64];
    for (int t = threadIdx.x; t < 4096; t += blockDim.x){
        int k = t >> 6, c = t & 63;
        sWt[c*64 + k] = W2[t];                       // transpose: contiguous over k
    }
    if (threadIdx.x < 64) sb[threadIdx.x] = b2[threadIdx.x];
    __syncthreads();
    int e = blockIdx.x*blockDim.x + threadIdx.x;
    int src, dst;
    if (g_ei32){
        const int* e32 = (const int*)ei;
        src = e32[e];                    // edge_index[0] = source j
        dst = e32[E_EDGES + e];          // edge_index[1] = target i
    } else {
        const long long* e64 = (const long long*)ei;
        src = (int)e64[e];
        dst = (int)e64[E_EDGES + e];
    }
    if ((unsigned)src < NN && (unsigned)dst < NN)
        edge_tail(dst, src, sWt, sb, g_x1);
}

__global__ void __launch_bounds__(256) k_ec2(const float* __restrict__ W4,
                                             const float* __restrict__ b4,
                                             float* __restrict__ out){
    __shared__ __align__(16) float sWt[64*64];
    __shared__ __align__(16) float sb[64];
    for (int t = threadIdx.x; t < 4096; t += blockDim.x){
        int k = t >> 6, c = t & 63;
        sWt[c*64 + k] = W4[t];
    }
    if (threadIdx.x < 64) sb[threadIdx.x] = b4[threadIdx.x];
    __syncthreads();
    int e = blockIdx.x*blockDim.x + threadIdx.x;
    int dst = e >> 4;
    int src = g_knn[e];
    edge_tail(dst, src, sWt, sb, out);
}

// ---------------- kNN: 1 row per thread, NSEG=2 segments, no register cap spills -------
// __launch_bounds__(128, 2): reg cap 255 (needs ~130-160) -> no spill; insert warp-any
// probability drops to ~36% with 8192-candidate scans.
__global__ void __launch_bounds__(128, 2) k_knn(){
    __shared__ __align__(16) float sxj[JCHUNK*64];
    __shared__ float ssq[JCHUNK];
    int tid = threadIdx.x;
    int row = blockIdx.x*128 + tid;
    int j0  = blockIdx.y*JSEG;

    unsigned long long xi[32];
    {
        const ulonglong2* xp = (const ulonglong2*)(g_x1 + row*64);
#pragma unroll
        for (int q = 0; q < 16; q++){ ulonglong2 t = xp[q]; xi[2*q] = t.x; xi[2*q+1] = t.y; }
    }
    float sqi = g_sq[row];

    float bd[16]; int bi[16];
#pragma unroll
    for (int t = 0; t < 16; t++){ bd[t] = __int_as_float(0x7f800000); bi[t] = 0x7fffffff; }
    float mx = __int_as_float(0x7f800000); int mxi = 0x7fffffff;

    for (int ch = 0; ch < JSEG; ch += JCHUNK){
        __syncthreads();
        const float4* gs = (const float4*)(g_x1 + (size_t)(j0+ch)*64);
        float4* sd = (float4*)sxj;
#pragma unroll
        for (int t = 0; t < (JCHUNK*16)/128; t++) sd[tid + t*128] = gs[tid + t*128];
        if (tid < JCHUNK) ssq[tid] = g_sq[j0 + ch + tid];
        __syncthreads();

        for (int jj = 0; jj < JCHUNK; jj++){
            const ulonglong2* sp = (const ulonglong2*)(sxj + jj*64);
            unsigned long long a0 = 0ull, a1 = 0ull, a2 = 0ull, a3 = 0ull;
#pragma unroll
            for (int q = 0; q < 16; q += 2){
                ulonglong2 w0 = sp[q], w1 = sp[q+1];
                fma2(a0, xi[2*q  ], w0.x);
                fma2(a1, xi[2*q+1], w0.y);
                fma2(a2, xi[2*q+2], w1.x);
                fma2(a3, xi[2*q+3], w1.y);
            }
            float2 r0 = upk2(a0), r1 = upk2(a1), r2 = upk2(a2), r3 = upk2(a3);
            float dot = ((r0.x+r0.y)+(r1.x+r1.y)) + ((r2.x+r2.y)+(r3.x+r3.y));
            float d = sqi + ssq[jj] - 2.f*dot;
            // ascending j + strict < reproduces lax.top_k tie order exactly
            if (d < mx){
                t16_insert(bd, bi, d, j0 + ch + jj, mx, mxi);
            }
        }
    }
    int base = (blockIdx.y*NN + row)*KNB;
#pragma unroll
    for (int t = 0; t < 16; t++){ g_pd[base+t] = bd[t]; g_pi[base+t] = bi[t]; }
}

// ---------------- merge per-segment top-16s into global top-16 set ----------------
__global__ void __launch_bounds__(256) k_merge(){
    int i = blockIdx.x*blockDim.x + threadIdx.x;
    float bd[16]; int bi[16];
#pragma unroll
    for (int t = 0; t < 16; t++){ bd[t] = __int_as_float(0x7f800000); bi[t] = 0x7fffffff; }
    float mx = __int_as_float(0x7f800000); int mxi = 0x7fffffff;
    for (int s = 0; s < NSEG; s++){
        int base = (s*NN + i)*KNB;
#pragma unroll
        for (int t = 0; t < 16; t++){
            float d = g_pd[base+t]; int j = g_pi[base+t];
            if (d < mx || (d == mx && j < mxi)){
                t16_insert(bd, bi, d, j, mx, mxi);
            }
        }
    }
#pragma unroll
    for (int t = 0; t < 16; t++) g_knn[i*KNB + t] = bi[t];
}

// ---------------- launch ----------------
extern "C" void kernel_launch(void* const* d_in, const int* in_sizes, int n_in,
                              void* d_out, int out_size){
    const float* x  = (const float*)d_in[0];
    const void*  ei = d_in[1];
    int off = (n_in > 2 && in_sizes[2] == 1) ? 3 : 2;
    const float* W1 = (const float*)d_in[off+0];
    const float* b1 = (const float*)d_in[off+1];
    const float* W2 = (const float*)d_in[off+2];
    const float* b2 = (const float*)d_in[off+3];
    const float* W3 = (const float*)d_in[off+4];
    const float* b3 = (const float*)d_in[off+5];
    const float* W4 = (const float*)d_in[off+6];
    const float* b4 = (const float*)d_in[off+7];
    float* out = (float*)d_out;

    k_detect<<<1, 256>>>((const int*)ei);
    k_init<<<(NN*64)/256, 256>>>(out);
    // EdgeConv1
    k_node<3, false, false><<<NN/256, 256>>>(x, W1, b1);
    k_ec1<<<E_EDGES/256, 256>>>(ei, W2, b2);
    // node-level work for EdgeConv2 layer-1 + sq-norms of x1 for kNN
    k_node<64, true, true><<<NN/256, 256>>>(nullptr, W3, b3);
    // kNN in x1 feature space (1 row/thread, 2 j-segments)
    dim3 kg(NN/128, NSEG);
    k_knn<<<kg, 128>>>();
    k_merge<<<NN/256, 256>>>();
    // EdgeConv2
    k_ec2<<<(NN*KNB)/256, 256>>>(W4, b4, out);
    (void)in_sizes; (void)n_in; (void)out_size;
}